// round 2
// baseline (speedup 1.0000x reference)
#include <cuda_runtime.h>
#include <math.h>

#define NB   32      // batch
#define PP   196     // pixels
#define ENC  2048
#define DECD 512
#define ATT  512
#define EMB  256
#define NV   30000
#define LL   21
#define NT   20      // decode steps

typedef unsigned long long u64;

// ---------- packed f32x2 helpers (sm_103a) ----------
__device__ __forceinline__ u64 pack2(float lo, float hi) {
    u64 r; asm("mov.b64 %0, {%1, %2};" : "=l"(r) : "f"(lo), "f"(hi)); return r;
}
__device__ __forceinline__ void unpack2(u64 v, float& lo, float& hi) {
    asm("mov.b64 {%0, %1}, %2;" : "=f"(lo), "=f"(hi) : "l"(v));
}
__device__ __forceinline__ u64 ffma2(u64 a, u64 b, u64 c) {
    u64 d; asm("fma.rn.f32x2 %0, %1, %2, %3;" : "=l"(d) : "l"(a), "l"(b), "l"(c)); return d;
}
__device__ __forceinline__ u64 fadd2(u64 a, u64 b) {
    u64 d; asm("add.rn.f32x2 %0, %1, %2;" : "=l"(d) : "l"(a), "l"(b)); return d;
}

// ---------- persistent scratch (no cudaMalloc allowed) ----------
__device__ __align__(16) float g_att1 [NB * PP * ATT];     // 12.8 MB
__device__ __align__(16) float g_mean [NB * ENC];
__device__ __align__(16) float g_h    [NB * DECD];
__device__ __align__(16) float g_c    [NB * DECD];
__device__ __align__(16) float g_att2 [NB * ATT];
__device__ __align__(16) float g_alpha[NB * PP];
__device__ __align__(16) float g_x    [NB * (EMB + ENC)];
__device__ __align__(16) float g_gates[NB * 4 * DECD];

// ============================================================
// mean over P:  g_mean[b][k] = mean_p enc[b][p][k]
// ============================================================
__global__ void mean_kernel(const float* __restrict__ enc, float* __restrict__ mean)
{
    int b = blockIdx.x;
    for (int k = threadIdx.x; k < ENC; k += 256) {
        const float* p0 = enc + (size_t)b * PP * ENC + k;
        float s = 0.f;
        #pragma unroll 4
        for (int p = 0; p < PP; p++) s += p0[(size_t)p * ENC];
        mean[b * ENC + k] = s * (1.0f / PP);
    }
}

// ============================================================
// att1 GEMM: C[6272,512] = A[6272,2048] @ W[512,2048]^T + bias
// 128x64 block tile, BK=32, per-thread 8m x 4n via f32x2 m-pairs
// ============================================================
__global__ __launch_bounds__(256) void att1_gemm_kernel(
    const float* __restrict__ A, const float* __restrict__ W,
    const float* __restrict__ bias, float* __restrict__ C)
{
    __shared__ __align__(16) float As[32][128];
    __shared__ __align__(16) float Bs[32][64];
    const int tid = threadIdx.x;
    const int m0  = blockIdx.y * 128;
    const int n0  = blockIdx.x * 64;
    const int tmb = (tid & 15) * 2;      // m base (pair start), strided pairs at +32*i
    const int tn  = (tid >> 4) * 4;      // 4 consecutive n

    u64 acc[4][4];
    #pragma unroll
    for (int i = 0; i < 4; i++)
        #pragma unroll
        for (int j = 0; j < 4; j++) acc[i][j] = 0ull;

    for (int k0 = 0; k0 < ENC; k0 += 32) {
        float4 av[4], bv[2];
        #pragma unroll
        for (int r = 0; r < 4; r++) {
            int f = tid + r * 256; int m = f >> 3; int c = f & 7;
            av[r] = *(const float4*)(A + (size_t)(m0 + m) * ENC + k0 + c * 4);
        }
        #pragma unroll
        for (int r = 0; r < 2; r++) {
            int f = tid + r * 256; int n = f >> 3; int c = f & 7;
            bv[r] = *(const float4*)(W + (size_t)(n0 + n) * ENC + k0 + c * 4);
        }
        __syncthreads();
        #pragma unroll
        for (int r = 0; r < 4; r++) {
            int f = tid + r * 256; int m = f >> 3; int c = f & 7;
            As[c*4+0][m] = av[r].x; As[c*4+1][m] = av[r].y;
            As[c*4+2][m] = av[r].z; As[c*4+3][m] = av[r].w;
        }
        #pragma unroll
        for (int r = 0; r < 2; r++) {
            int f = tid + r * 256; int n = f >> 3; int c = f & 7;
            Bs[c*4+0][n] = bv[r].x; Bs[c*4+1][n] = bv[r].y;
            Bs[c*4+2][n] = bv[r].z; Bs[c*4+3][n] = bv[r].w;
        }
        __syncthreads();
        #pragma unroll 8
        for (int k = 0; k < 32; k++) {
            u64 a2[4];
            #pragma unroll
            for (int i = 0; i < 4; i++)
                a2[i] = *(const u64*)&As[k][tmb + 32 * i];
            float4 b4 = *(const float4*)&Bs[k][tn];
            u64 bd[4] = { pack2(b4.x, b4.x), pack2(b4.y, b4.y),
                          pack2(b4.z, b4.z), pack2(b4.w, b4.w) };
            #pragma unroll
            for (int i = 0; i < 4; i++)
                #pragma unroll
                for (int j = 0; j < 4; j++)
                    acc[i][j] = ffma2(a2[i], bd[j], acc[i][j]);
        }
    }
    #pragma unroll
    for (int i = 0; i < 4; i++) {
        int m = m0 + tmb + 32 * i;
        #pragma unroll
        for (int j = 0; j < 4; j++) {
            int n = n0 + tn + j;
            float lo, hi; unpack2(acc[i][j], lo, hi);
            float bb = bias[n];
            C[(size_t)m       * ATT + n] = lo + bb;
            C[(size_t)(m + 1) * ATT + n] = hi + bb;
        }
    }
}

// ============================================================
// Skinny GEMM: out[b][n] = bias1[n](+bias2[n]) + A1[b]·W1[n] (+ A2[b]·W2[n])
// 32 batch rows x 16 n per block; batch packed in pairs (f32x2).
// K (each segment) must be a multiple of 64.
// ============================================================
__global__ __launch_bounds__(256) void skinny_gemm_kernel(
    const float* __restrict__ A1, const float* __restrict__ W1, int K1,
    const float* __restrict__ A2, const float* __restrict__ W2, int K2,
    const float* __restrict__ bias1, const float* __restrict__ bias2,
    float* __restrict__ out, int ldc)
{
    __shared__ __align__(16) u64 xs[16][64];   // [b-pair][k-in-tile]
    const int tid  = threadIdx.x;
    const int lane = tid & 31;
    const int w    = tid >> 5;
    const int ng   = w & 3;      // 4 n-groups
    const int bg   = w >> 2;     // 2 b-groups (8 pairs each)
    const int n0   = blockIdx.x * 16 + ng * 4;
    const int b2s  = tid >> 4;   // staging: pair index 0..15
    const int c4   = tid & 15;   // staging: float4 column 0..15

    u64 acc[8][4];
    #pragma unroll
    for (int i = 0; i < 8; i++)
        #pragma unroll
        for (int j = 0; j < 4; j++) acc[i][j] = 0ull;

    #pragma unroll 1
    for (int seg = 0; seg < 2; seg++) {
        const float* A = seg ? A2 : A1;
        const float* W = seg ? W2 : W1;
        const int    K = seg ? K2 : K1;
        if (A == nullptr) continue;
        for (int k0 = 0; k0 < K; k0 += 64) {
            float4 lo4 = *(const float4*)(A + (size_t)(2 * b2s)     * K + k0 + c4 * 4);
            float4 hi4 = *(const float4*)(A + (size_t)(2 * b2s + 1) * K + k0 + c4 * 4);
            __syncthreads();
            xs[b2s][c4*4+0] = pack2(lo4.x, hi4.x);
            xs[b2s][c4*4+1] = pack2(lo4.y, hi4.y);
            xs[b2s][c4*4+2] = pack2(lo4.z, hi4.z);
            xs[b2s][c4*4+3] = pack2(lo4.w, hi4.w);
            __syncthreads();
            const float* wp = W + k0 + lane;
            u64 wd0[4], wd1[4];
            #pragma unroll
            for (int j = 0; j < 4; j++) {
                const float* r = wp + (size_t)(n0 + j) * K;
                float w0 = r[0], w1 = r[32];
                wd0[j] = pack2(w0, w0);
                wd1[j] = pack2(w1, w1);
            }
            #pragma unroll
            for (int i = 0; i < 8; i++) {
                u64 x0 = xs[bg * 8 + i][lane];
                u64 x1 = xs[bg * 8 + i][lane + 32];
                #pragma unroll
                for (int j = 0; j < 4; j++) {
                    acc[i][j] = ffma2(x0, wd0[j], acc[i][j]);
                    acc[i][j] = ffma2(x1, wd1[j], acc[i][j]);
                }
            }
        }
    }
    // cross-lane reduction (each lane held a disjoint k subset)
    #pragma unroll
    for (int i = 0; i < 8; i++)
        #pragma unroll
        for (int j = 0; j < 4; j++) {
            u64 v = acc[i][j];
            #pragma unroll
            for (int o = 16; o > 0; o >>= 1)
                v = fadd2(v, __shfl_xor_sync(0xffffffffu, v, o));
            acc[i][j] = v;
        }
    if (lane == 0) {
        #pragma unroll
        for (int i = 0; i < 8; i++) {
            int b = (bg * 8 + i) * 2;
            #pragma unroll
            for (int j = 0; j < 4; j++) {
                int n = n0 + j;
                float bb = bias1[n] + (bias2 ? bias2[n] : 0.0f);
                float lo, hi; unpack2(acc[i][j], lo, hi);
                out[(size_t)b       * ldc + n] = lo + bb;
                out[(size_t)(b + 1) * ldc + n] = hi + bb;
            }
        }
    }
}

// ============================================================
// e[b,p] = bf + sum_a Wf[a] * relu(att1[b,p,a] + att2[b,a])   (warp per (b,p))
// ============================================================
__global__ void escore_kernel(const float* __restrict__ att1,
                              const float* __restrict__ att2,
                              const float* __restrict__ Wf,
                              const float* __restrict__ bf,
                              float* __restrict__ e_out)
{
    int wglob = blockIdx.x * 8 + (threadIdx.x >> 5);
    int lane  = threadIdx.x & 31;
    int b = wglob / PP, p = wglob % PP;
    const float4* t1 = (const float4*)(att1 + (size_t)(b * PP + p) * ATT);
    const float4* t2 = (const float4*)(att2 + (size_t)b * ATT);
    const float4* wf = (const float4*)Wf;
    float acc = 0.f;
    #pragma unroll
    for (int c = lane; c < ATT / 4; c += 32) {
        float4 a = t1[c], h = t2[c], v = wf[c];
        acc += fmaxf(a.x + h.x, 0.f) * v.x + fmaxf(a.y + h.y, 0.f) * v.y
             + fmaxf(a.z + h.z, 0.f) * v.z + fmaxf(a.w + h.w, 0.f) * v.w;
    }
    #pragma unroll
    for (int o = 16; o > 0; o >>= 1) acc += __shfl_xor_sync(0xffffffffu, acc, o);
    if (lane == 0) e_out[b * PP + p] = acc + bf[0];
}

// ============================================================
// softmax over P (per b) + write alphas output + gather caption embedding
// ============================================================
__global__ void softmax_emb_kernel(float* __restrict__ alpha,        // in: e, out: alpha
                                   float* __restrict__ out_alpha, int t,
                                   const int* __restrict__ captions, // int32 view
                                   const float* __restrict__ emb,
                                   float* __restrict__ xbuf)
{
    __shared__ float red[256];
    __shared__ int s_idx;
    int b = blockIdx.x, tid = threadIdx.x;
    float v = (tid < PP) ? alpha[b * PP + tid] : -3.4e38f;
    red[tid] = v; __syncthreads();
    #pragma unroll
    for (int s = 128; s > 0; s >>= 1) {
        if (tid < s) red[tid] = fmaxf(red[tid], red[tid + s]);
        __syncthreads();
    }
    float mx = red[0]; __syncthreads();
    float ex = (tid < PP) ? expf(v - mx) : 0.f;
    red[tid] = ex; __syncthreads();
    #pragma unroll
    for (int s = 128; s > 0; s >>= 1) {
        if (tid < s) red[tid] += red[tid + s];
        __syncthreads();
    }
    float inv = 1.0f / red[0];
    if (tid < PP) {
        float a = ex * inv;
        alpha[b * PP + tid] = a;
        out_alpha[(size_t)(b * NT + t) * PP + tid] = a;
    }
    if (tid == 0) {
        // dtype hedge: if captions arrived as int64, every odd 32-bit word is 0
        bool is64 = true;
        #pragma unroll
        for (int i = 0; i < 32; i++)
            if (captions[2 * i + 1] != 0) is64 = false;
        int pos = b * LL + t;
        s_idx = is64 ? captions[2 * pos] : captions[pos];
    }
    __syncthreads();
    xbuf[(size_t)b * (EMB + ENC) + tid] = emb[(size_t)s_idx * EMB + tid];  // 256 threads == EMB
}

// ============================================================
// awe[b][k] = sum_p alpha[b,p] * enc[b,p,k]  -> written into x buffer at +EMB
// ============================================================
__global__ void awe_kernel(const float* __restrict__ enc,
                           const float* __restrict__ alpha,
                           float* __restrict__ xbuf)
{
    __shared__ float al[PP];
    int b = blockIdx.y;
    int k = blockIdx.x * 256 + threadIdx.x;
    if (threadIdx.x < PP) al[threadIdx.x] = alpha[b * PP + threadIdx.x];
    __syncthreads();
    const float* ep = enc + (size_t)b * PP * ENC + k;
    float acc = 0.f;
    #pragma unroll 4
    for (int p = 0; p < PP; p++) acc += al[p] * ep[(size_t)p * ENC];
    xbuf[(size_t)b * (EMB + ENC) + EMB + k] = acc;
}

// ============================================================
// LSTM pointwise (PyTorch gate order i,f,g,o)
// ============================================================
__global__ void lstm_kernel(const float* __restrict__ gates,
                            float* __restrict__ h, float* __restrict__ c)
{
    int i = blockIdx.x * 256 + threadIdx.x;   // 32*512
    int b = i >> 9, j = i & 511;
    const float* g = gates + (size_t)b * 4 * DECD;
    float ig = g[j], fg = g[DECD + j], gg = g[2 * DECD + j], og = g[3 * DECD + j];
    float si = 1.f / (1.f + expf(-ig));
    float sf = 1.f / (1.f + expf(-fg));
    float so = 1.f / (1.f + expf(-og));
    float cn = sf * c[i] + si * tanhf(gg);
    float hn = so * tanhf(cn);
    c[i] = cn; h[i] = hn;
}

// ============================================================
extern "C" void kernel_launch(void* const* d_in, const int* in_sizes, int n_in,
                              void* d_out, int out_size)
{
    const float* enc  = (const float*)d_in[0];
    const int*   caps = (const int*)  d_in[1];
    // d_in[2] caption_lengths: unused by the reference computation
    const float* emb  = (const float*)d_in[3];
    const float* We   = (const float*)d_in[4];
    const float* be   = (const float*)d_in[5];
    const float* Wd   = (const float*)d_in[6];
    const float* bd   = (const float*)d_in[7];
    const float* Wf   = (const float*)d_in[8];
    const float* bf   = (const float*)d_in[9];
    const float* Wih  = (const float*)d_in[10];
    const float* bih  = (const float*)d_in[11];
    const float* Whh  = (const float*)d_in[12];
    const float* bhh  = (const float*)d_in[13];
    const float* Wfc  = (const float*)d_in[14];
    const float* bfc  = (const float*)d_in[15];
    const float* Wh0  = (const float*)d_in[16];
    const float* bh0  = (const float*)d_in[17];
    const float* Wc0  = (const float*)d_in[18];
    const float* bc0  = (const float*)d_in[19];

    float* out       = (float*)d_out;                       // predictions [32,20,30000]
    float* out_alpha = out + (size_t)NB * NT * NV;          // alphas      [32,20,196]

    float *p_att1, *p_mean, *p_h, *p_c, *p_att2, *p_alpha, *p_x, *p_gates;
    cudaGetSymbolAddress((void**)&p_att1,  g_att1);
    cudaGetSymbolAddress((void**)&p_mean,  g_mean);
    cudaGetSymbolAddress((void**)&p_h,     g_h);
    cudaGetSymbolAddress((void**)&p_c,     g_c);
    cudaGetSymbolAddress((void**)&p_att2,  g_att2);
    cudaGetSymbolAddress((void**)&p_alpha, g_alpha);
    cudaGetSymbolAddress((void**)&p_x,     g_x);
    cudaGetSymbolAddress((void**)&p_gates, g_gates);

    // ---- init: mean pool, h0/c0, att1 projection ----
    mean_kernel<<<NB, 256>>>(enc, p_mean);
    skinny_gemm_kernel<<<DECD / 16, 256>>>(p_mean, Wh0, ENC, nullptr, nullptr, 0,
                                           bh0, nullptr, p_h, DECD);
    skinny_gemm_kernel<<<DECD / 16, 256>>>(p_mean, Wc0, ENC, nullptr, nullptr, 0,
                                           bc0, nullptr, p_c, DECD);
    att1_gemm_kernel<<<dim3(ATT / 64, (NB * PP) / 128), 256>>>(enc, We, be, p_att1);

    // ---- decode loop ----
    for (int t = 0; t < NT; t++) {
        skinny_gemm_kernel<<<ATT / 16, 256>>>(p_h, Wd, DECD, nullptr, nullptr, 0,
                                              bd, nullptr, p_att2, ATT);
        escore_kernel<<<(NB * PP) / 8, 256>>>(p_att1, p_att2, Wf, bf, p_alpha);
        softmax_emb_kernel<<<NB, 256>>>(p_alpha, out_alpha, t, caps, emb, p_x);
        awe_kernel<<<dim3(ENC / 256, NB), 256>>>(enc, p_alpha, p_x);
        skinny_gemm_kernel<<<(4 * DECD) / 16, 256>>>(p_x, Wih, EMB + ENC,
                                                     p_h, Whh, DECD,
                                                     bih, bhh, p_gates, 4 * DECD);
        lstm_kernel<<<(NB * DECD) / 256, 256>>>(p_gates, p_h, p_c);
        skinny_gemm_kernel<<<NV / 16, 256>>>(p_h, Wfc, DECD, nullptr, nullptr, 0,
                                             bfc, nullptr, out + (size_t)t * NV, NT * NV);
    }
}